// round 1
// baseline (speedup 1.0000x reference)
#include <cuda_runtime.h>
#include <math.h>

#define B_ 4
#define C_ 64
#define N_ 4096

// Scratch (device globals — no allocation allowed in kernel_launch)
__device__ float g_q[B_ * C_ * N_];  // [b][c][n] channel-major
__device__ float g_k[B_ * C_ * N_];  // [b][c][n] channel-major
__device__ float g_v[B_ * N_ * C_];  // [b][n][c] token-major

// ---------------------------------------------------------------------------
// QKV projection: q/k/v = W @ x + b  (1x1 conv == per-token linear)
// Block: 64-token tile of one batch. 256 threads, 4x4 microtiles.
// ---------------------------------------------------------------------------
__global__ __launch_bounds__(256, 1) void qkv_kernel(
    const float* __restrict__ x,
    const float* __restrict__ Wq, const float* __restrict__ bq,
    const float* __restrict__ Wk, const float* __restrict__ bk,
    const float* __restrict__ Wv, const float* __restrict__ bv)
{
    __shared__ float xs[C_ * 64];   // xs[c][tn]
    __shared__ float ws[C_ * C_];   // W[o][c]
    __shared__ float bs[C_];

    const int t  = threadIdx.x;
    const int b  = blockIdx.y;
    const int n0 = blockIdx.x * 64;

    // Load x tile [64 c][64 tn], coalesced float4
    #pragma unroll
    for (int k = 0; k < 4; k++) {
        int e = t + k * 256;
        int c = e >> 4, tn4 = (e & 15) << 2;
        *(float4*)&xs[c * 64 + tn4] =
            *(const float4*)&x[(b * C_ + c) * N_ + n0 + tn4];
    }

    const int tng = t & 15, og = t >> 4;
    const int tn0 = tng * 4, o0 = og * 4;

    const float* Wm[3] = {Wq, Wk, Wv};
    const float* bm[3] = {bq, bk, bv};

    #pragma unroll 1
    for (int m = 0; m < 3; m++) {
        __syncthreads();
        #pragma unroll
        for (int k = 0; k < 4; k++) {
            int e = (t + k * 256) * 4;
            *(float4*)&ws[e] = *(const float4*)&Wm[m][e];
        }
        if (t < C_) bs[t] = bm[m][t];
        __syncthreads();

        float acc[4][4];  // acc[oo][tt]
        #pragma unroll
        for (int oo = 0; oo < 4; oo++) {
            float bb = bs[o0 + oo];
            #pragma unroll
            for (int tt = 0; tt < 4; tt++) acc[oo][tt] = bb;
        }

        #pragma unroll 4
        for (int c = 0; c < C_; c++) {
            float xv[4];
            *(float4*)xv = *(float4*)&xs[c * 64 + tn0];
            #pragma unroll
            for (int oo = 0; oo < 4; oo++) {
                float w = ws[(o0 + oo) * C_ + c];
                #pragma unroll
                for (int tt = 0; tt < 4; tt++) acc[oo][tt] += w * xv[tt];
            }
        }

        if (m < 2) {
            float* dst = (m == 0) ? g_q : g_k;
            #pragma unroll
            for (int oo = 0; oo < 4; oo++)
                *(float4*)&dst[(b * C_ + o0 + oo) * N_ + n0 + tn0] =
                    make_float4(acc[oo][0], acc[oo][1], acc[oo][2], acc[oo][3]);
        } else {
            #pragma unroll
            for (int tt = 0; tt < 4; tt++)
                *(float4*)&g_v[(b * N_ + n0 + tn0 + tt) * C_ + o0] =
                    make_float4(acc[0][tt], acc[1][tt], acc[2][tt], acc[3][tt]);
        }
    }
}

// ---------------------------------------------------------------------------
// Attention: flash-style, 64 queries/block, 64-key tiles, no max-rescale
// (logits <= ~50 so exp/sums stay far inside fp32 range).
// smem = 48 KB exactly: Qs[c][i], KP (K tile [c][j], reused as P tile [j][i]),
// Vs[j][c]. 4x4 register microtiles; all LDS are float4, conflict-free.
// ---------------------------------------------------------------------------
__global__ __launch_bounds__(256, 1) void attn_kernel(float* __restrict__ out)
{
    __shared__ float Qs[C_ * 64];
    __shared__ float KP[64 * 64];
    __shared__ float Vs[64 * 64];

    const int t   = threadIdx.x;
    const int b   = blockIdx.y;
    const int qi0 = blockIdx.x * 64;

    // Load Q tile [c][i]
    #pragma unroll
    for (int k = 0; k < 4; k++) {
        int e = t + k * 256;
        int c = e >> 4, i4 = (e & 15) << 2;
        *(float4*)&Qs[c * 64 + i4] =
            *(const float4*)&g_q[(b * C_ + c) * N_ + qi0 + i4];
    }

    const int ig = t & 15, jg = t >> 4;
    const int i0 = ig * 4;        // query rows owned (both phases)
    const int j0 = jg * 4;        // key cols owned (S phase)
    const int c0 = jg * 4;        // channels owned (PV phase)

    float o[4][4];  // o[cc][ii] output accumulators
    float rs[4];    // row-sum partials for i0..i0+3 over this thread's j slice
    #pragma unroll
    for (int a = 0; a < 4; a++) {
        rs[a] = 0.f;
        #pragma unroll
        for (int e = 0; e < 4; e++) o[a][e] = 0.f;
    }

    for (int kt = 0; kt < N_ / 64; kt++) {
        const int kj0 = kt * 64;
        __syncthreads();  // previous tile's P/V fully consumed

        // Load K tile [c][j] into KP, V tile [j][c] into Vs (coalesced float4)
        #pragma unroll
        for (int k = 0; k < 4; k++) {
            int e = t + k * 256;
            int c = e >> 4, j4 = (e & 15) << 2;
            *(float4*)&KP[c * 64 + j4] =
                *(const float4*)&g_k[(b * C_ + c) * N_ + kj0 + j4];
        }
        #pragma unroll
        for (int k = 0; k < 4; k++) {
            int e = t + k * 256;
            int j = e >> 4, c4 = (e & 15) << 2;
            *(float4*)&Vs[j * 64 + c4] =
                *(const float4*)&g_v[(b * N_ + kj0 + j) * C_ + c4];
        }
        __syncthreads();

        // S = Q^T K : s[jj][ii], 2 LDS.128 per 16 FFMA
        float s[4][4];
        #pragma unroll
        for (int a = 0; a < 4; a++)
            #pragma unroll
            for (int e = 0; e < 4; e++) s[a][e] = 0.f;

        #pragma unroll 8
        for (int c = 0; c < C_; c++) {
            float qv[4], kv[4];
            *(float4*)qv = *(float4*)&Qs[c * 64 + i0];
            *(float4*)kv = *(float4*)&KP[c * 64 + j0];
            #pragma unroll
            for (int jj = 0; jj < 4; jj++)
                #pragma unroll
                for (int ii = 0; ii < 4; ii++)
                    s[jj][ii] += kv[jj] * qv[ii];
        }
        __syncthreads();  // all K reads done; KP becomes P

        // P = exp(S), store [j][i]; accumulate row-sum partials
        #pragma unroll
        for (int jj = 0; jj < 4; jj++) {
            float p[4];
            #pragma unroll
            for (int ii = 0; ii < 4; ii++) {
                p[ii] = __expf(s[jj][ii]);
                rs[ii] += p[ii];
            }
            *(float4*)&KP[(j0 + jj) * 64 + i0] =
                make_float4(p[0], p[1], p[2], p[3]);
        }
        __syncthreads();

        // O += P V : o[cc][ii]
        #pragma unroll 8
        for (int j = 0; j < 64; j++) {
            float pv[4], vv[4];
            *(float4*)pv = *(float4*)&KP[j * 64 + i0];
            *(float4*)vv = *(float4*)&Vs[j * 64 + c0];
            #pragma unroll
            for (int cc = 0; cc < 4; cc++)
                #pragma unroll
                for (int ii = 0; ii < 4; ii++)
                    o[cc][ii] += pv[ii] * vv[cc];
        }
    }

    // Reduce row-sums across the 16 jg partials (reuse KP)
    __syncthreads();
    *(float4*)&KP[jg * 64 + i0] = make_float4(rs[0], rs[1], rs[2], rs[3]);
    __syncthreads();

    float inv[4];
    #pragma unroll
    for (int ii = 0; ii < 4; ii++) {
        float sum = 0.f;
        #pragma unroll
        for (int g = 0; g < 16; g++) sum += KP[g * 64 + i0 + ii];
        inv[ii] = 1.f / sum;
    }

    // out[b][c][i] (matches [B,C,H,W] linearization), coalesced float4
    #pragma unroll
    for (int cc = 0; cc < 4; cc++)
        *(float4*)&out[(b * C_ + c0 + cc) * N_ + qi0 + i0] =
            make_float4(o[cc][0] * inv[0], o[cc][1] * inv[1],
                        o[cc][2] * inv[2], o[cc][3] * inv[3]);
}

// ---------------------------------------------------------------------------
// Inputs (metadata order): x, t(unused), Wq, bq, Wk, bk, Wv, bv
// ---------------------------------------------------------------------------
extern "C" void kernel_launch(void* const* d_in, const int* in_sizes, int n_in,
                              void* d_out, int out_size) {
    const float* x  = (const float*)d_in[0];
    const float* Wq = (const float*)d_in[2];
    const float* bq = (const float*)d_in[3];
    const float* Wk = (const float*)d_in[4];
    const float* bk = (const float*)d_in[5];
    const float* Wv = (const float*)d_in[6];
    const float* bv = (const float*)d_in[7];
    float* out = (float*)d_out;

    dim3 blk(256);
    dim3 grid(N_ / 64, B_);
    qkv_kernel<<<grid, blk>>>(x, Wq, bq, Wk, bk, Wv, bv);
    attn_kernel<<<grid, blk>>>(out);
}

// round 3
// speedup vs baseline: 3.5584x; 3.5584x over previous
#include <cuda_runtime.h>
#include <cuda_fp16.h>
#include <cstdint>

#define B_ 4
#define C_ 64
#define N_ 4096
#define TQ 128
#define TK 64
#define NT (N_/TK)
#define LOG2E 1.4426950408889634f
#define ONES16 0x3C003C00u

// Fragment-ordered scratch (written by qkv, read by attn). uint4-aligned.
// g_qf: [b][rowblk N/16][hl][cstep 4][lane 32]  (A-frag of m16n8k16, 4 u32)
// g_kf: [b][jblk N/64][hl][cstep 4][jpair 4][lane 32]  (B-frag pairs, 4 u32)
// g_vf: [b][jblk]    [hl][kstep 4][cpair 4][lane 32]
__device__ uint4 g_qf[4 * 256 * 2 * 4 * 32];
__device__ uint4 g_kf[4 * 64 * 2 * 4 * 4 * 32];
__device__ uint4 g_vf[4 * 64 * 2 * 4 * 4 * 32];

// ---------------------------------------------------------------------------
// helpers
// ---------------------------------------------------------------------------
__device__ __forceinline__ void cp16(uint32_t d, const void* g) {
    asm volatile("cp.async.cg.shared.global [%0], [%1], 16;"
                 :: "r"(d), "l"(__cvta_generic_to_global(g)) : "memory");
}
__device__ __forceinline__ uint4 lds128(uint32_t a) {
    uint4 r;
    asm volatile("ld.shared.v4.u32 {%0,%1,%2,%3}, [%4];"
                 : "=r"(r.x), "=r"(r.y), "=r"(r.z), "=r"(r.w) : "r"(a));
    return r;
}
__device__ __forceinline__ void mma16816(float* d, const uint32_t* a,
                                         uint32_t b0, uint32_t b1) {
    asm volatile("mma.sync.aligned.m16n8k16.row.col.f32.f16.f16.f32 "
        "{%0,%1,%2,%3}, {%4,%5,%6,%7}, {%8,%9}, {%0,%1,%2,%3};"
        : "+f"(d[0]), "+f"(d[1]), "+f"(d[2]), "+f"(d[3])
        : "r"(a[0]), "r"(a[1]), "r"(a[2]), "r"(a[3]), "r"(b0), "r"(b1));
}
__device__ __forceinline__ uint32_t cvtpk(float hi, float lo) {  // {hi,lo} f16x2
    uint32_t r;
    asm("cvt.rn.f16x2.f32 %0, %1, %2;" : "=r"(r) : "f"(hi), "f"(lo));
    return r;
}
__device__ __forceinline__ uint32_t ex2x2(uint32_t a) {
    uint32_t r;
    asm("ex2.approx.f16x2 %0, %1;" : "=r"(r) : "r"(a));
    return r;
}
__device__ __forceinline__ float ex2f(float x) {
    float r;
    asm("ex2.approx.f32 %0, %1;" : "=f"(r) : "f"(x));
    return r;
}
__device__ __forceinline__ uint32_t pkh(float x0, float x1) {  // lo=x0
    __half h0 = __float2half_rn(x0), h1 = __float2half_rn(x1);
    return ((uint32_t)__half_as_ushort(h1) << 16) | __half_as_ushort(h0);
}

__device__ __forceinline__ void copy_tile(uint32_t sdst, int b, int jt, int tid) {
    const uint4* gk = g_kf + ((size_t)b * 64 + jt) * 1024;
    const uint4* gv = g_vf + ((size_t)b * 64 + jt) * 1024;
    #pragma unroll
    for (int k = 0; k < 4; k++) {
        int idx = tid + k * 256;
        cp16(sdst + idx * 16, gk + idx);
        cp16(sdst + 16384 + idx * 16, gv + idx);
    }
}

// ---------------------------------------------------------------------------
// Flash attention: 128 q-rows/CTA (8 warps x 16 rows), 64-key tiles,
// fp16 mma.sync, fp32 accum, online max, ones-column rowsum.
// ---------------------------------------------------------------------------
__global__ void __launch_bounds__(256, 1) attn_tc(float* __restrict__ out)
{
    extern __shared__ uint8_t smraw[];
    const uint32_t smbase = (uint32_t)__cvta_generic_to_shared(smraw);
    const int tid = threadIdx.x, w = tid >> 5, lane = tid & 31;
    const int g = lane >> 2, tq = lane & 3;
    const int b = blockIdx.x >> 5, qblk = blockIdx.x & 31;

    // persistent Q fragments (hi/lo), 32 regs
    uint32_t qh[4][4], ql[4][4];
    {
        const uint4* qp = g_qf + ((size_t)(b * 256 + qblk * 8 + w)) * 256 + lane;
        #pragma unroll
        for (int cs = 0; cs < 4; cs++) {
            uint4 h = qp[cs * 32];
            qh[cs][0] = h.x; qh[cs][1] = h.y; qh[cs][2] = h.z; qh[cs][3] = h.w;
            uint4 l = qp[128 + cs * 32];
            ql[cs][0] = l.x; ql[cs][1] = l.y; ql[cs][2] = l.z; ql[cs][3] = l.w;
        }
    }

    float o[9][4];   // 8 n-blocks of output + block 8 = rowsum (ones column)
    #pragma unroll
    for (int nb = 0; nb < 9; nb++)
        #pragma unroll
        for (int i = 0; i < 4; i++) o[nb][i] = 0.f;
    float m0 = -1e30f, m1 = -1e30f;

    copy_tile(smbase, b, 0, tid);
    asm volatile("cp.async.commit_group;" ::: "memory");

    for (int t = 0; t < NT; t++) {
        if (t + 1 < NT) {
            copy_tile(smbase + ((t + 1) & 1) * 32768, b, t + 1, tid);
            asm volatile("cp.async.commit_group;" ::: "memory");
            asm volatile("cp.async.wait_group 1;" ::: "memory");
        } else {
            asm volatile("cp.async.wait_group 0;" ::: "memory");
        }
        __syncthreads();
        const uint32_t sK = smbase + (t & 1) * 32768;
        const uint32_t sV = sK + 16384;

        // --- S = Q K^T (hi*hi + lo*hi + hi*lo) ---
        float s[8][4];
        #pragma unroll
        for (int nb = 0; nb < 8; nb++)
            #pragma unroll
            for (int i = 0; i < 4; i++) s[nb][i] = 0.f;

        #pragma unroll
        for (int cs = 0; cs < 4; cs++) {
            #pragma unroll
            for (int jp = 0; jp < 4; jp++) {
                uint4 KH = lds128(sK + ((0 + cs) * 4 + jp) * 512 + lane * 16);
                uint4 KL = lds128(sK + ((4 + cs) * 4 + jp) * 512 + lane * 16);
                mma16816(s[2*jp],   qh[cs], KH.x, KH.y);
                mma16816(s[2*jp],   ql[cs], KH.x, KH.y);
                mma16816(s[2*jp],   qh[cs], KL.x, KL.y);
                mma16816(s[2*jp+1], qh[cs], KH.z, KH.w);
                mma16816(s[2*jp+1], ql[cs], KH.z, KH.w);
                mma16816(s[2*jp+1], qh[cs], KL.z, KL.w);
            }
        }

        // --- online softmax (log2 domain) ---
        #pragma unroll
        for (int nb = 0; nb < 8; nb++)
            #pragma unroll
            for (int i = 0; i < 4; i++) s[nb][i] *= LOG2E;

        float t0 = -1e30f, t1 = -1e30f;
        #pragma unroll
        for (int nb = 0; nb < 8; nb++) {
            t0 = fmaxf(t0, fmaxf(s[nb][0], s[nb][1]));
            t1 = fmaxf(t1, fmaxf(s[nb][2], s[nb][3]));
        }
        t0 = fmaxf(t0, __shfl_xor_sync(0xffffffffu, t0, 1));
        t0 = fmaxf(t0, __shfl_xor_sync(0xffffffffu, t0, 2));
        t1 = fmaxf(t1, __shfl_xor_sync(0xffffffffu, t1, 1));
        t1 = fmaxf(t1, __shfl_xor_sync(0xffffffffu, t1, 2));
        const float m0n = fmaxf(m0, t0), m1n = fmaxf(m1, t1);
        const float a0 = ex2f(m0 - m0n), a1 = ex2f(m1 - m1n);
        m0 = m0n; m1 = m1n;

        #pragma unroll
        for (int nb = 0; nb < 9; nb++) {
            o[nb][0] *= a0; o[nb][1] *= a0; o[nb][2] *= a1; o[nb][3] *= a1;
        }

        uint32_t p[8][2];
        #pragma unroll
        for (int nb = 0; nb < 8; nb++) {
            p[nb][0] = ex2x2(cvtpk(s[nb][1] - m0, s[nb][0] - m0));
            p[nb][1] = ex2x2(cvtpk(s[nb][3] - m1, s[nb][2] - m1));
        }

        // --- O += P V  (+ ones-column rowsum) ---
        #pragma unroll
        for (int s4 = 0; s4 < 4; s4++) {
            uint32_t a[4] = { p[2*s4][0], p[2*s4][1], p[2*s4+1][0], p[2*s4+1][1] };
            #pragma unroll
            for (int cp = 0; cp < 4; cp++) {
                uint4 VH = lds128(sV + ((0 + s4) * 4 + cp) * 512 + lane * 16);
                uint4 VL = lds128(sV + ((4 + s4) * 4 + cp) * 512 + lane * 16);
                mma16816(o[2*cp],   a, VH.x, VH.y);
                mma16816(o[2*cp],   a, VL.x, VL.y);
                mma16816(o[2*cp+1], a, VH.z, VH.w);
                mma16816(o[2*cp+1], a, VL.z, VL.w);
            }
            mma16816(o[8], a, ONES16, ONES16);
        }
        __syncthreads();
    }

    // --- epilogue: divide by rowsum, write out[b][c][row] ---
    const float i0 = 1.f / o[8][0], i1 = 1.f / o[8][2];
    const int row0 = qblk * 128 + w * 16 + g;
    #pragma unroll
    for (int nb = 0; nb < 8; nb++) {
        const int c0 = nb * 8 + 2 * tq;
        out[((size_t)b * 64 + c0) * 4096 + row0]         = o[nb][0] * i0;
        out[((size_t)b * 64 + c0 + 1) * 4096 + row0]     = o[nb][1] * i0;
        out[((size_t)b * 64 + c0) * 4096 + row0 + 8]     = o[nb][2] * i1;
        out[((size_t)b * 64 + c0 + 1) * 4096 + row0 + 8] = o[nb][3] * i1;
    }
}

// ---------------------------------------------------------------------------
// QKV projection; emits Q/K/V in MMA-fragment order (fp16 hi/lo splits).
// ---------------------------------------------------------------------------
__global__ void __launch_bounds__(256, 1) qkv_kernel(
    const float* __restrict__ x,
    const float* __restrict__ Wq, const float* __restrict__ bq,
    const float* __restrict__ Wk, const float* __restrict__ bk,
    const float* __restrict__ Wv, const float* __restrict__ bv)
{
    __shared__ float xs[C_ * 64];
    __shared__ float ws[C_ * C_];
    __shared__ float bs[C_];

    const int t  = threadIdx.x;
    const int b  = blockIdx.y;
    const int n0 = blockIdx.x * 64;

    #pragma unroll
    for (int k = 0; k < 4; k++) {
        int e = t + k * 256;
        int c = e >> 4, tn4 = (e & 15) << 2;
        *(float4*)&xs[c * 64 + tn4] = *(const float4*)&x[(b * C_ + c) * N_ + n0 + tn4];
    }

    const int tng = t & 15, og = t >> 4;
    const int tn0 = tng * 4, o0 = og * 4;

    const float* Wm[3] = {Wq, Wk, Wv};
    const float* bm[3] = {bq, bk, bv};

    #pragma unroll 1
    for (int m = 0; m < 3; m++) {
        __syncthreads();
        #pragma unroll
        for (int k = 0; k < 4; k++) {
            int e = (t + k * 256) * 4;
            *(float4*)&ws[e] = *(const float4*)&Wm[m][e];
        }
        if (t < C_) bs[t] = bm[m][t];
        __syncthreads();

        float acc[4][4];
        #pragma unroll
        for (int oo = 0; oo < 4; oo++) {
            float bb = bs[o0 + oo];
            #pragma unroll
            for (int tt = 0; tt < 4; tt++) acc[oo][tt] = bb;
        }
        #pragma unroll 4
        for (int c = 0; c < C_; c++) {
            float xv[4];
            *(float4*)xv = *(float4*)&xs[c * 64 + tn0];
            #pragma unroll
            for (int oo = 0; oo < 4; oo++) {
                float w = ws[(o0 + oo) * C_ + c];
                #pragma unroll
                for (int tt = 0; tt < 4; tt++) acc[oo][tt] += w * xv[tt];
            }
        }

        if (m < 2) {
            uint32_t* dst = (uint32_t*)((m == 0) ? g_qf : g_kf);
            #pragma unroll
            for (int tt = 0; tt < 4; tt++) {
                int n = n0 + tn0 + tt;
                #pragma unroll
                for (int op = 0; op < 2; op++) {
                    int c = o0 + 2 * op;
                    float x0 = acc[2*op][tt], x1 = acc[2*op+1][tt];
                    __half h0 = __float2half_rn(x0), h1 = __float2half_rn(x1);
                    uint32_t hi_w = ((uint32_t)__half_as_ushort(h1) << 16)
                                  | __half_as_ushort(h0);
                    uint32_t lo_w = pkh(x0 - __half2float(h0), x1 - __half2float(h1));
                    size_t a0, hstride;
                    if (m == 0) {  // Q: A-frag [b][rowblk][hl][cstep][lane][4]
                        int rowblk = n >> 4, r = n & 15, gg = r & 7, hb = (r >> 3) & 1;
                        int cs = c >> 4, cc = c & 15;
                        int lane_ = gg * 4 + ((cc & 7) >> 1);
                        int idx = hb + ((cc >> 3) << 1);
                        a0 = ((((size_t)(b * 256 + rowblk) * 2) * 4 + cs) * 32 + lane_) * 4 + idx;
                        hstride = (size_t)4 * 32 * 4;
                    } else {       // K: B-frag [b][jblk][hl][cstep][jpair][lane][4]
                        int jblk = n >> 6, jj = n & 63;
                        int cs = c >> 4, nb = jj >> 3, jp = nb >> 1, bsel = nb & 1;
                        int lane_ = (jj & 7) * 4 + ((c & 7) >> 1);
                        int idx = bsel * 2 + ((c & 15) >> 3);
                        a0 = (((((size_t)(b * 64 + jblk) * 2) * 4 + cs) * 4 + jp) * 32 + lane_) * 4 + idx;
                        hstride = (size_t)4 * 4 * 32 * 4;
                    }
                    dst[a0] = hi_w;
                    dst[a0 + hstride] = lo_w;
                }
            }
        } else {  // V: B-frag k=token, n=channel: [b][jblk][hl][kstep][cpair][lane][4]
            uint32_t* dst = (uint32_t*)g_vf;
            const int jblk = n0 >> 6;
            #pragma unroll
            for (int oo = 0; oo < 4; oo++) {
                int c = o0 + oo;
                #pragma unroll
                for (int tp = 0; tp < 2; tp++) {
                    int jj = tn0 + 2 * tp;
                    float x0 = acc[oo][2*tp], x1 = acc[oo][2*tp+1];
                    __half h0 = __float2half_rn(x0), h1 = __float2half_rn(x1);
                    uint32_t hi_w = ((uint32_t)__half_as_ushort(h1) << 16)
                                  | __half_as_ushort(h0);
                    uint32_t lo_w = pkh(x0 - __half2float(h0), x1 - __half2float(h1));
                    int ks = jj >> 4, cp = c >> 4, bsel = (c >> 3) & 1;
                    int lane_ = (c & 7) * 4 + ((jj & 7) >> 1);
                    int idx = bsel * 2 + ((jj & 15) >> 3);
                    size_t a0 = (((((size_t)(b * 64 + jblk) * 2) * 4 + ks) * 4 + cp) * 32 + lane_) * 4 + idx;
                    dst[a0] = hi_w;
                    dst[a0 + (size_t)4 * 4 * 32 * 4] = lo_w;
                }
            }
        }
    }
}

// ---------------------------------------------------------------------------
// Inputs (metadata order): x, t(unused), Wq, bq, Wk, bk, Wv, bv
// ---------------------------------------------------------------------------
extern "C" void kernel_launch(void* const* d_in, const int* in_sizes, int n_in,
                              void* d_out, int out_size) {
    const float* x  = (const float*)d_in[0];
    const float* Wq = (const float*)d_in[2];
    const float* bq = (const float*)d_in[3];
    const float* Wk = (const float*)d_in[4];
    const float* bk = (const float*)d_in[5];
    const float* Wv = (const float*)d_in[6];
    const float* bv = (const float*)d_in[7];
    float* out = (float*)d_out;

    cudaFuncSetAttribute(attn_tc, cudaFuncAttributeMaxDynamicSharedMemorySize,
                         65536);
    qkv_kernel<<<dim3(N_ / 64, B_), 256>>>(x, Wq, bq, Wk, bk, Wv, bv);
    attn_tc<<<B_ * (N_ / TQ), 256, 65536>>>(out);
}

// round 4
// speedup vs baseline: 4.0984x; 1.1518x over previous
#include <cuda_runtime.h>
#include <cuda_fp16.h>
#include <cstdint>

#define B_ 4
#define C_ 64
#define N_ 4096
#define TK 64
#define NT (N_/TK)
#define LOG2E 1.4426950408889634f
#define ONES16 0x3C003C00u

// Fragment-ordered scratch (written by qkv, read by attn). uint4-aligned.
// g_qf: [b][rowblk N/16][hl][cstep 4][lane 32]  (A-frag of m16n8k16, 4 u32)
// g_kf: [b][jblk N/64][hl][cstep 4][jpair 4][lane 32]  (B-frag pairs, 4 u32)
// g_vf: [b][jblk][kstep 4][cpair 4][lane 32]   (hi only)
__device__ uint4 g_qf[4 * 256 * 2 * 4 * 32];
__device__ uint4 g_kf[4 * 64 * 2 * 4 * 4 * 32];
__device__ uint4 g_vf[4 * 64 * 4 * 4 * 32];

// ---------------------------------------------------------------------------
// helpers
// ---------------------------------------------------------------------------
__device__ __forceinline__ void cp16(uint32_t d, const void* g) {
    asm volatile("cp.async.cg.shared.global [%0], [%1], 16;"
                 :: "r"(d), "l"(__cvta_generic_to_global(g)) : "memory");
}
__device__ __forceinline__ uint4 lds128(uint32_t a) {
    uint4 r;
    asm volatile("ld.shared.v4.u32 {%0,%1,%2,%3}, [%4];"
                 : "=r"(r.x), "=r"(r.y), "=r"(r.z), "=r"(r.w) : "r"(a));
    return r;
}
__device__ __forceinline__ void mma16816(float* d, const uint32_t* a,
                                         uint32_t b0, uint32_t b1) {
    asm volatile("mma.sync.aligned.m16n8k16.row.col.f32.f16.f16.f32 "
        "{%0,%1,%2,%3}, {%4,%5,%6,%7}, {%8,%9}, {%0,%1,%2,%3};"
        : "+f"(d[0]), "+f"(d[1]), "+f"(d[2]), "+f"(d[3])
        : "r"(a[0]), "r"(a[1]), "r"(a[2]), "r"(a[3]), "r"(b0), "r"(b1));
}
__device__ __forceinline__ uint32_t cvtpk(float hi, float lo) {
    uint32_t r;
    asm("cvt.rn.f16x2.f32 %0, %1, %2;" : "=r"(r) : "f"(hi), "f"(lo));
    return r;
}
__device__ __forceinline__ uint32_t ex2x2(uint32_t a) {
    uint32_t r;
    asm("ex2.approx.f16x2 %0, %1;" : "=r"(r) : "r"(a));
    return r;
}
__device__ __forceinline__ float ex2f(float x) {
    float r;
    asm("ex2.approx.f32 %0, %1;" : "=f"(r) : "f"(x));
    return r;
}
__device__ __forceinline__ uint32_t pkh(float x0, float x1) {
    __half h0 = __float2half_rn(x0), h1 = __float2half_rn(x1);
    return ((uint32_t)__half_as_ushort(h1) << 16) | __half_as_ushort(h0);
}

// K tile (hi+lo, 1024 u4) + V tile (hi, 512 u4) -> 24 KB, 128 threads
__device__ __forceinline__ void copy_tile(uint32_t sdst, int b, int jt, int tid) {
    const uint4* gk = g_kf + ((size_t)b * 64 + jt) * 1024;
    const uint4* gv = g_vf + ((size_t)b * 64 + jt) * 512;
    #pragma unroll
    for (int k = 0; k < 8; k++) {
        int idx = tid + k * 128;
        cp16(sdst + idx * 16, gk + idx);
    }
    #pragma unroll
    for (int k = 0; k < 4; k++) {
        int idx = tid + k * 128;
        cp16(sdst + 16384 + idx * 16, gv + idx);
    }
}

// ---------------------------------------------------------------------------
// Flash attention: 64 q-rows/CTA (4 warps x 16 rows), 64-key tiles,
// fp16 mma.sync, fp32 accum, online max, ones-column rowsum.
// 2 CTAs/SM so one CTA's MMAs overlap the other's softmax.
// ---------------------------------------------------------------------------
__global__ void __launch_bounds__(128, 2) attn_tc(float* __restrict__ out)
{
    extern __shared__ uint8_t smraw[];
    const uint32_t smbase = (uint32_t)__cvta_generic_to_shared(smraw);
    const int tid = threadIdx.x, w = tid >> 5, lane = tid & 31;
    const int g = lane >> 2, tq = lane & 3;
    const int b = blockIdx.x >> 6, qblk = blockIdx.x & 63;

    // persistent Q fragments (hi/lo), 32 regs
    uint32_t qh[4][4], ql[4][4];
    {
        const uint4* qp = g_qf + ((size_t)(b * 256 + qblk * 4 + w)) * 256 + lane;
        #pragma unroll
        for (int cs = 0; cs < 4; cs++) {
            uint4 h = qp[cs * 32];
            qh[cs][0] = h.x; qh[cs][1] = h.y; qh[cs][2] = h.z; qh[cs][3] = h.w;
            uint4 l = qp[128 + cs * 32];
            ql[cs][0] = l.x; ql[cs][1] = l.y; ql[cs][2] = l.z; ql[cs][3] = l.w;
        }
    }

    float o[9][4];   // 8 n-blocks of output + block 8 = rowsum (ones column)
    #pragma unroll
    for (int nb = 0; nb < 9; nb++)
        #pragma unroll
        for (int i = 0; i < 4; i++) o[nb][i] = 0.f;
    float m0 = -1e30f, m1 = -1e30f;

    copy_tile(smbase, b, 0, tid);
    asm volatile("cp.async.commit_group;" ::: "memory");

    for (int t = 0; t < NT; t++) {
        if (t + 1 < NT) {
            copy_tile(smbase + ((t + 1) & 1) * 24576, b, t + 1, tid);
            asm volatile("cp.async.commit_group;" ::: "memory");
            asm volatile("cp.async.wait_group 1;" ::: "memory");
        } else {
            asm volatile("cp.async.wait_group 0;" ::: "memory");
        }
        __syncthreads();
        const uint32_t sK = smbase + (t & 1) * 24576;
        const uint32_t sV = sK + 16384;

        // --- S = Q K^T (hi*hi + lo*hi + hi*lo) ---
        float s[8][4];
        #pragma unroll
        for (int nb = 0; nb < 8; nb++)
            #pragma unroll
            for (int i = 0; i < 4; i++) s[nb][i] = 0.f;

        #pragma unroll
        for (int cs = 0; cs < 4; cs++) {
            #pragma unroll
            for (int jp = 0; jp < 4; jp++) {
                uint4 KH = lds128(sK + ((0 + cs) * 4 + jp) * 512 + lane * 16);
                uint4 KL = lds128(sK + ((4 + cs) * 4 + jp) * 512 + lane * 16);
                mma16816(s[2*jp],   qh[cs], KH.x, KH.y);
                mma16816(s[2*jp],   ql[cs], KH.x, KH.y);
                mma16816(s[2*jp],   qh[cs], KL.x, KL.y);
                mma16816(s[2*jp+1], qh[cs], KH.z, KH.w);
                mma16816(s[2*jp+1], ql[cs], KH.z, KH.w);
                mma16816(s[2*jp+1], qh[cs], KL.z, KL.w);
            }
        }

        // --- online softmax (log2 domain) ---
        #pragma unroll
        for (int nb = 0; nb < 8; nb++)
            #pragma unroll
            for (int i = 0; i < 4; i++) s[nb][i] *= LOG2E;

        float t0 = -1e30f, t1 = -1e30f;
        #pragma unroll
        for (int nb = 0; nb < 8; nb++) {
            t0 = fmaxf(t0, fmaxf(s[nb][0], s[nb][1]));
            t1 = fmaxf(t1, fmaxf(s[nb][2], s[nb][3]));
        }
        t0 = fmaxf(t0, __shfl_xor_sync(0xffffffffu, t0, 1));
        t0 = fmaxf(t0, __shfl_xor_sync(0xffffffffu, t0, 2));
        t1 = fmaxf(t1, __shfl_xor_sync(0xffffffffu, t1, 1));
        t1 = fmaxf(t1, __shfl_xor_sync(0xffffffffu, t1, 2));
        const float m0n = fmaxf(m0, t0), m1n = fmaxf(m1, t1);
        const float a0 = ex2f(m0 - m0n), a1 = ex2f(m1 - m1n);
        m0 = m0n; m1 = m1n;

        #pragma unroll
        for (int nb = 0; nb < 9; nb++) {
            o[nb][0] *= a0; o[nb][1] *= a0; o[nb][2] *= a1; o[nb][3] *= a1;
        }

        uint32_t p[8][2];
        #pragma unroll
        for (int nb = 0; nb < 8; nb++) {
            p[nb][0] = ex2x2(cvtpk(s[nb][1] - m0, s[nb][0] - m0));
            p[nb][1] = ex2x2(cvtpk(s[nb][3] - m1, s[nb][2] - m1));
        }

        // --- O += P V (V hi only) + ones-column rowsum ---
        #pragma unroll
        for (int s4 = 0; s4 < 4; s4++) {
            uint32_t a[4] = { p[2*s4][0], p[2*s4][1], p[2*s4+1][0], p[2*s4+1][1] };
            #pragma unroll
            for (int cp = 0; cp < 4; cp++) {
                uint4 VH = lds128(sV + (s4 * 4 + cp) * 512 + lane * 16);
                mma16816(o[2*cp],   a, VH.x, VH.y);
                mma16816(o[2*cp+1], a, VH.z, VH.w);
            }
            mma16816(o[8], a, ONES16, ONES16);
        }
        __syncthreads();
    }

    // --- epilogue: divide by rowsum, stage via smem for coalesced stores ---
    float* sm = (float*)smraw;  // stride-68 staging, conflict-free
    const float i0 = 1.f / o[8][0], i1 = 1.f / o[8][2];
    const int r0 = w * 16 + g;
    #pragma unroll
    for (int nb = 0; nb < 8; nb++) {
        const int c0 = nb * 8 + 2 * tq;
        sm[c0 * 68 + r0]           = o[nb][0] * i0;
        sm[(c0 + 1) * 68 + r0]     = o[nb][1] * i0;
        sm[c0 * 68 + r0 + 8]       = o[nb][2] * i1;
        sm[(c0 + 1) * 68 + r0 + 8] = o[nb][3] * i1;
    }
    __syncthreads();
    #pragma unroll
    for (int k = 0; k < 8; k++) {
        int idx = tid + k * 128;
        int c = idx >> 4, i4 = (idx & 15) << 2;
        *(float4*)&out[((size_t)b * 64 + c) * 4096 + qblk * 64 + i4] =
            *(float4*)&sm[c * 68 + i4];
    }
}

// ---------------------------------------------------------------------------
// QKV projection; emits Q/K (fp16 hi/lo) and V (fp16 hi) in MMA-frag order.
// ---------------------------------------------------------------------------
__global__ void __launch_bounds__(256, 1) qkv_kernel(
    const float* __restrict__ x,
    const float* __restrict__ Wq, const float* __restrict__ bq,
    const float* __restrict__ Wk, const float* __restrict__ bk,
    const float* __restrict__ Wv, const float* __restrict__ bv)
{
    __shared__ float xs[C_ * 64];
    __shared__ float ws[C_ * C_];
    __shared__ float bs[C_];

    const int t  = threadIdx.x;
    const int b  = blockIdx.y;
    const int n0 = blockIdx.x * 64;

    #pragma unroll
    for (int k = 0; k < 4; k++) {
        int e = t + k * 256;
        int c = e >> 4, tn4 = (e & 15) << 2;
        *(float4*)&xs[c * 64 + tn4] = *(const float4*)&x[(b * C_ + c) * N_ + n0 + tn4];
    }

    const int tng = t & 15, og = t >> 4;
    const int tn0 = tng * 4, o0 = og * 4;

    const float* Wm[3] = {Wq, Wk, Wv};
    const float* bm[3] = {bq, bk, bv};

    #pragma unroll 1
    for (int m = 0; m < 3; m++) {
        __syncthreads();
        #pragma unroll
        for (int k = 0; k < 4; k++) {
            int e = (t + k * 256) * 4;
            *(float4*)&ws[e] = *(const float4*)&Wm[m][e];
        }
        if (t < C_) bs[t] = bm[m][t];
        __syncthreads();

        float acc[4][4];
        #pragma unroll
        for (int oo = 0; oo < 4; oo++) {
            float bb = bs[o0 + oo];
            #pragma unroll
            for (int tt = 0; tt < 4; tt++) acc[oo][tt] = bb;
        }
        #pragma unroll 4
        for (int c = 0; c < C_; c++) {
            float xv[4];
            *(float4*)xv = *(float4*)&xs[c * 64 + tn0];
            #pragma unroll
            for (int oo = 0; oo < 4; oo++) {
                float w = ws[(o0 + oo) * C_ + c];
                #pragma unroll
                for (int tt = 0; tt < 4; tt++) acc[oo][tt] += w * xv[tt];
            }
        }

        if (m < 2) {
            uint32_t* dst = (uint32_t*)((m == 0) ? g_qf : g_kf);
            #pragma unroll
            for (int tt = 0; tt < 4; tt++) {
                int n = n0 + tn0 + tt;
                #pragma unroll
                for (int op = 0; op < 2; op++) {
                    int c = o0 + 2 * op;
                    float x0 = acc[2*op][tt], x1 = acc[2*op+1][tt];
                    __half h0 = __float2half_rn(x0), h1 = __float2half_rn(x1);
                    uint32_t hi_w = ((uint32_t)__half_as_ushort(h1) << 16)
                                  | __half_as_ushort(h0);
                    uint32_t lo_w = pkh(x0 - __half2float(h0), x1 - __half2float(h1));
                    size_t a0, hstride;
                    if (m == 0) {  // Q: A-frag [b][rowblk][hl][cstep][lane][4]
                        int rowblk = n >> 4, r = n & 15, gg = r & 7, hb = (r >> 3) & 1;
                        int cs = c >> 4, cc = c & 15;
                        int lane_ = gg * 4 + ((cc & 7) >> 1);
                        int idx = hb + ((cc >> 3) << 1);
                        a0 = ((((size_t)(b * 256 + rowblk) * 2) * 4 + cs) * 32 + lane_) * 4 + idx;
                        hstride = (size_t)4 * 32 * 4;
                    } else {       // K: B-frag [b][jblk][hl][cstep][jpair][lane][4]
                        int jblk = n >> 6, jj = n & 63;
                        int cs = c >> 4, nb = jj >> 3, jp = nb >> 1, bsel = nb & 1;
                        int lane_ = (jj & 7) * 4 + ((c & 7) >> 1);
                        int idx = bsel * 2 + ((c & 15) >> 3);
                        a0 = (((((size_t)(b * 64 + jblk) * 2) * 4 + cs) * 4 + jp) * 32 + lane_) * 4 + idx;
                        hstride = (size_t)4 * 4 * 32 * 4;
                    }
                    dst[a0] = hi_w;
                    dst[a0 + hstride] = lo_w;
                }
            }
        } else {  // V hi only: [b][jblk][kstep][cpair][lane][4]
            uint32_t* dst = (uint32_t*)g_vf;
            const int jblk = n0 >> 6;
            #pragma unroll
            for (int oo = 0; oo < 4; oo++) {
                int c = o0 + oo;
                #pragma unroll
                for (int tp = 0; tp < 2; tp++) {
                    int jj = tn0 + 2 * tp;
                    uint32_t hi_w = pkh(acc[oo][2*tp], acc[oo][2*tp+1]);
                    int ks = jj >> 4, cp = c >> 4, bsel = (c >> 3) & 1;
                    int lane_ = (c & 7) * 4 + ((jj & 7) >> 1);
                    int idx = bsel * 2 + ((jj & 15) >> 3);
                    size_t a0 = ((((size_t)(b * 64 + jblk) * 4 + ks) * 4 + cp) * 32 + lane_) * 4 + idx;
                    dst[a0] = hi_w;
                }
            }
        }
    }
}

// ---------------------------------------------------------------------------
// Inputs (metadata order): x, t(unused), Wq, bq, Wk, bk, Wv, bv
// ---------------------------------------------------------------------------
extern "C" void kernel_launch(void* const* d_in, const int* in_sizes, int n_in,
                              void* d_out, int out_size) {
    const float* x  = (const float*)d_in[0];
    const float* Wq = (const float*)d_in[2];
    const float* bq = (const float*)d_in[3];
    const float* Wk = (const float*)d_in[4];
    const float* bk = (const float*)d_in[5];
    const float* Wv = (const float*)d_in[6];
    const float* bv = (const float*)d_in[7];
    float* out = (float*)d_out;

    cudaFuncSetAttribute(attn_tc, cudaFuncAttributeMaxDynamicSharedMemorySize,
                         49152);
    qkv_kernel<<<dim3(N_ / 64, B_), 256>>>(x, Wq, bq, Wk, bk, Wv, bv);
    attn_tc<<<B_ * 64, 128, 49152>>>(out);
}

// round 5
// speedup vs baseline: 4.3465x; 1.0605x over previous
#include <cuda_runtime.h>
#include <cuda_fp16.h>
#include <cstdint>

#define B_ 4
#define C_ 64
#define N_ 4096
#define NT2 32              // 4096 / 128-key tiles
#define LOG2E 1.4426950408889634f
#define ONES16 0x3C003C00u

// Fragment-ordered scratch. uint4 units.
// g_qf: [b][rowblk N/16][hl][cstep 4][lane 32]            (A-frag, LOG2E-folded)
// g_kf: [b][jblk N/64][hl][cstep 4][jpair 4][lane 32]     (B-frag pairs)
// g_vf: [b][jblk][kstep 4][cpair 4][lane 32]              (hi only)
__device__ uint4 g_qf[4 * 256 * 2 * 4 * 32];
__device__ uint4 g_kf[4 * 64 * 2 * 4 * 4 * 32];
__device__ uint4 g_vf[4 * 64 * 4 * 4 * 32];

// ---------------------------------------------------------------------------
__device__ __forceinline__ void cp16(uint32_t d, const void* g) {
    asm volatile("cp.async.cg.shared.global [%0], [%1], 16;"
                 :: "r"(d), "l"(__cvta_generic_to_global(g)) : "memory");
}
__device__ __forceinline__ uint4 lds128(uint32_t a) {
    uint4 r;
    asm volatile("ld.shared.v4.u32 {%0,%1,%2,%3}, [%4];"
                 : "=r"(r.x), "=r"(r.y), "=r"(r.z), "=r"(r.w) : "r"(a));
    return r;
}
__device__ __forceinline__ void mma16816(float* d, const uint32_t* a,
                                         uint32_t b0, uint32_t b1) {
    asm volatile("mma.sync.aligned.m16n8k16.row.col.f32.f16.f16.f32 "
        "{%0,%1,%2,%3}, {%4,%5,%6,%7}, {%8,%9}, {%0,%1,%2,%3};"
        : "+f"(d[0]), "+f"(d[1]), "+f"(d[2]), "+f"(d[3])
        : "r"(a[0]), "r"(a[1]), "r"(a[2]), "r"(a[3]), "r"(b0), "r"(b1));
}
__device__ __forceinline__ uint32_t cvtpk(float hi, float lo) {
    uint32_t r;
    asm("cvt.rn.f16x2.f32 %0, %1, %2;" : "=r"(r) : "f"(hi), "f"(lo));
    return r;
}
__device__ __forceinline__ uint32_t ex2x2(uint32_t a) {
    uint32_t r;
    asm("ex2.approx.f16x2 %0, %1;" : "=r"(r) : "r"(a));
    return r;
}
__device__ __forceinline__ float ex2f(float x) {
    float r;
    asm("ex2.approx.f32 %0, %1;" : "=f"(r) : "f"(x));
    return r;
}
__device__ __forceinline__ uint32_t pkh(float x0, float x1) {
    __half h0 = __float2half_rn(x0), h1 = __float2half_rn(x1);
    return ((uint32_t)__half_as_ushort(h1) << 16) | __half_as_ushort(h0);
}

// 128-key tile: K(hi+lo) 32KB identity-copy + V(hi) 16KB. 128 threads.
__device__ __forceinline__ void copy_tile(uint32_t sdst, int b, int t2, int tid) {
    const uint4* gk = g_kf + ((size_t)b * 64 + t2 * 2) * 1024;
    const uint4* gv = g_vf + ((size_t)b * 64 + t2 * 2) * 512;
    #pragma unroll
    for (int k = 0; k < 16; k++) {
        int idx = tid + k * 128;
        cp16(sdst + idx * 16, gk + idx);
    }
    #pragma unroll
    for (int k = 0; k < 8; k++) {
        int idx = tid + k * 128;
        cp16(sdst + 32768 + idx * 16, gv + idx);
    }
}

// ---------------------------------------------------------------------------
// Flash attention: 64 q-rows/CTA (4 warps), 128-key tiles, fp16 mma.sync,
// fp32 accum, online max (log2 domain folded into Q), ones-column rowsum.
// ---------------------------------------------------------------------------
__global__ void __launch_bounds__(128, 2) attn_tc(float* __restrict__ out)
{
    extern __shared__ uint8_t smraw[];
    const uint32_t smbase = (uint32_t)__cvta_generic_to_shared(smraw);
    const int tid = threadIdx.x, w = tid >> 5, lane = tid & 31;
    const int g = lane >> 2, tq = lane & 3;
    const int b = blockIdx.x >> 6, qblk = blockIdx.x & 63;

    // persistent Q fragments (hi/lo), 32 regs
    uint32_t qh[4][4], ql[4][4];
    {
        const uint4* qp = g_qf + ((size_t)(b * 256 + qblk * 4 + w)) * 256 + lane;
        #pragma unroll
        for (int cs = 0; cs < 4; cs++) {
            uint4 h = qp[cs * 32];
            qh[cs][0] = h.x; qh[cs][1] = h.y; qh[cs][2] = h.z; qh[cs][3] = h.w;
            uint4 l = qp[128 + cs * 32];
            ql[cs][0] = l.x; ql[cs][1] = l.y; ql[cs][2] = l.z; ql[cs][3] = l.w;
        }
    }

    float o[9][4];
    #pragma unroll
    for (int nb = 0; nb < 9; nb++)
        #pragma unroll
        for (int i = 0; i < 4; i++) o[nb][i] = 0.f;
    float m0 = -1e30f, m1 = -1e30f;

    copy_tile(smbase, b, 0, tid);
    asm volatile("cp.async.commit_group;" ::: "memory");

    for (int t = 0; t < NT2; t++) {
        if (t + 1 < NT2) {
            copy_tile(smbase + ((t + 1) & 1) * 49152, b, t + 1, tid);
            asm volatile("cp.async.commit_group;" ::: "memory");
            asm volatile("cp.async.wait_group 1;" ::: "memory");
        } else {
            asm volatile("cp.async.wait_group 0;" ::: "memory");
        }
        __syncthreads();
        const uint32_t sK = smbase + (t & 1) * 49152;
        const uint32_t sV = sK + 32768;

        // --- S = Q K^T (hi*hi + lo*hi + hi*lo), 128 keys = 8 jpairs ---
        float s[16][4];
        #pragma unroll
        for (int nb = 0; nb < 16; nb++)
            #pragma unroll
            for (int i = 0; i < 4; i++) s[nb][i] = 0.f;

        #pragma unroll
        for (int cs = 0; cs < 4; cs++) {
            #pragma unroll
            for (int jp = 0; jp < 8; jp++) {
                uint32_t base = sK + (jp >> 2) * 16384
                              + (cs * 4 + (jp & 3)) * 512 + lane * 16;
                uint4 KH = lds128(base);
                uint4 KL = lds128(base + 8192);
                mma16816(s[2*jp],   qh[cs], KH.x, KH.y);
                mma16816(s[2*jp],   ql[cs], KH.x, KH.y);
                mma16816(s[2*jp],   qh[cs], KL.x, KL.y);
                mma16816(s[2*jp+1], qh[cs], KH.z, KH.w);
                mma16816(s[2*jp+1], ql[cs], KH.z, KH.w);
                mma16816(s[2*jp+1], qh[cs], KL.z, KL.w);
            }
        }

        // --- online softmax (log2 domain; LOG2E pre-folded into Q) ---
        float t0 = -1e30f, t1 = -1e30f;
        #pragma unroll
        for (int nb = 0; nb < 16; nb++) {
            t0 = fmaxf(t0, fmaxf(s[nb][0], s[nb][1]));
            t1 = fmaxf(t1, fmaxf(s[nb][2], s[nb][3]));
        }
        t0 = fmaxf(t0, __shfl_xor_sync(0xffffffffu, t0, 1));
        t0 = fmaxf(t0, __shfl_xor_sync(0xffffffffu, t0, 2));
        t1 = fmaxf(t1, __shfl_xor_sync(0xffffffffu, t1, 1));
        t1 = fmaxf(t1, __shfl_xor_sync(0xffffffffu, t1, 2));
        const float m0n = fmaxf(m0, t0), m1n = fmaxf(m1, t1);

        bool same = (m0n == m0) && (m1n == m1);
        if (__ballot_sync(0xffffffffu, same) != 0xffffffffu) {
            const float a0 = ex2f(m0 - m0n), a1 = ex2f(m1 - m1n);
            #pragma unroll
            for (int nb = 0; nb < 9; nb++) {
                o[nb][0] *= a0; o[nb][1] *= a0; o[nb][2] *= a1; o[nb][3] *= a1;
            }
        }
        m0 = m0n; m1 = m1n;

        uint32_t p[16][2];
        #pragma unroll
        for (int nb = 0; nb < 16; nb++) {
            p[nb][0] = ex2x2(cvtpk(s[nb][1] - m0, s[nb][0] - m0));
            p[nb][1] = ex2x2(cvtpk(s[nb][3] - m1, s[nb][2] - m1));
        }

        // --- O += P V (V hi only) + ones-column rowsum ---
        #pragma unroll
        for (int s4 = 0; s4 < 8; s4++) {
            uint32_t a[4] = { p[2*s4][0], p[2*s4][1], p[2*s4+1][0], p[2*s4+1][1] };
            #pragma unroll
            for (int cp = 0; cp < 4; cp++) {
                uint4 VH = lds128(sV + (s4 >> 2) * 8192
                                  + ((s4 & 3) * 4 + cp) * 512 + lane * 16);
                mma16816(o[2*cp],   a, VH.x, VH.y);
                mma16816(o[2*cp+1], a, VH.z, VH.w);
            }
            mma16816(o[8], a, ONES16, ONES16);
        }
        __syncthreads();
    }

    // --- epilogue: divide by rowsum, stage via smem for coalesced stores ---
    float* sm = (float*)smraw;  // stride-68 staging, conflict-free
    const float i0 = 1.f / o[8][0], i1 = 1.f / o[8][2];
    const int r0 = w * 16 + g;
    #pragma unroll
    for (int nb = 0; nb < 8; nb++) {
        const int c0 = nb * 8 + 2 * tq;
        sm[c0 * 68 + r0]           = o[nb][0] * i0;
        sm[(c0 + 1) * 68 + r0]     = o[nb][1] * i0;
        sm[c0 * 68 + r0 + 8]       = o[nb][2] * i1;
        sm[(c0 + 1) * 68 + r0 + 8] = o[nb][3] * i1;
    }
    __syncthreads();
    #pragma unroll
    for (int k = 0; k < 8; k++) {
        int idx = tid + k * 128;
        int c = idx >> 4, i4 = (idx & 15) << 2;
        *(float4*)&out[((size_t)b * 64 + c) * 4096 + qblk * 64 + i4] =
            *(float4*)&sm[c * 68 + i4];
    }
}

// ---------------------------------------------------------------------------
// QKV projection; fragments staged in smem, coalesced uint4 global stores.
// Q is scaled by LOG2E before hi/lo split.
// ---------------------------------------------------------------------------
__global__ void __launch_bounds__(256, 1) qkv_kernel(
    const float* __restrict__ x,
    const float* __restrict__ Wq, const float* __restrict__ bq,
    const float* __restrict__ Wk, const float* __restrict__ bk,
    const float* __restrict__ Wv, const float* __restrict__ bv)
{
    __shared__ float xs[4096];
    __shared__ __align__(16) float wstage[4096];  // W during compute, frags after
    __shared__ float bs[64];

    const int t  = threadIdx.x;
    const int b  = blockIdx.y;
    const int n0 = blockIdx.x * 64;

    #pragma unroll
    for (int k = 0; k < 4; k++) {
        int e = t + k * 256;
        int c = e >> 4, tn4 = (e & 15) << 2;
        *(float4*)&xs[c * 64 + tn4] = *(const float4*)&x[(b * C_ + c) * N_ + n0 + tn4];
    }

    const int tng = t & 15, og = t >> 4;
    const int tn0 = tng * 4, o0 = og * 4;

    const float* Wm[3] = {Wq, Wk, Wv};
    const float* bm[3] = {bq, bk, bv};

    #pragma unroll 1
    for (int m = 0; m < 3; m++) {
        __syncthreads();  // prior copy-out done before W reload
        #pragma unroll
        for (int k = 0; k < 4; k++) {
            int e = (t + k * 256) * 4;
            *(float4*)&wstage[e] = *(const float4*)&Wm[m][e];
        }
        if (t < C_) bs[t] = bm[m][t];
        __syncthreads();

        float acc[4][4];
        #pragma unroll
        for (int oo = 0; oo < 4; oo++) {
            float bb = bs[o0 + oo];
            #pragma unroll
            for (int tt = 0; tt < 4; tt++) acc[oo][tt] = bb;
        }
        #pragma unroll 4
        for (int c = 0; c < C_; c++) {
            float xv[4];
            *(float4*)xv = *(float4*)&xs[c * 64 + tn0];
            #pragma unroll
            for (int oo = 0; oo < 4; oo++) {
                float w = wstage[(o0 + oo) * C_ + c];
                #pragma unroll
                for (int tt = 0; tt < 4; tt++) acc[oo][tt] += w * xv[tt];
            }
        }
        if (m == 0) {  // fold LOG2E into Q
            #pragma unroll
            for (int oo = 0; oo < 4; oo++)
                #pragma unroll
                for (int tt = 0; tt < 4; tt++) acc[oo][tt] *= LOG2E;
        }
        __syncthreads();  // all W reads done; wstage becomes frag staging

        uint32_t* stage = (uint32_t*)wstage;
        if (m < 2) {
            #pragma unroll
            for (int tt = 0; tt < 4; tt++) {
                int n = n0 + tn0 + tt;
                #pragma unroll
                for (int op = 0; op < 2; op++) {
                    int c = o0 + 2 * op;
                    float x0 = acc[2*op][tt], x1 = acc[2*op+1][tt];
                    __half h0 = __float2half_rn(x0), h1 = __float2half_rn(x1);
                    uint32_t hi_w = ((uint32_t)__half_as_ushort(h1) << 16)
                                  | __half_as_ushort(h0);
                    uint32_t lo_w = pkh(x0 - __half2float(h0), x1 - __half2float(h1));
                    int loff, plane;
                    if (m == 0) {  // [rbl][hl][cs][lane][4]
                        int rbl = (n >> 4) & 3, r = n & 15, gg = r & 7, hb = (r >> 3) & 1;
                        int cs = c >> 4, cc = c & 15;
                        int lane_ = gg * 4 + ((cc & 7) >> 1);
                        int idx = hb + ((cc >> 3) << 1);
                        loff = (((rbl * 2) * 4 + cs) * 32 + lane_) * 4 + idx;
                        plane = 512;
                    } else {       // [hl][cs][jp][lane][4]
                        int jj = n & 63;
                        int cs = c >> 4, nb = jj >> 3, jp = nb >> 1, bsel = nb & 1;
                        int lane_ = (jj & 7) * 4 + ((c & 7) >> 1);
                        int idx = bsel * 2 + ((c & 15) >> 3);
                        loff = ((cs * 4 + jp) * 32 + lane_) * 4 + idx;
                        plane = 2048;
                    }
                    stage[loff] = hi_w;
                    stage[loff + plane] = lo_w;
                }
            }
        } else {  // V hi only: [ks][cp][lane][4]
            #pragma unroll
            for (int oo = 0; oo < 4; oo++) {
                int c = o0 + oo;
                #pragma unroll
                for (int tp = 0; tp < 2; tp++) {
                    int jj = tn0 + 2 * tp;
                    uint32_t hi_w = pkh(acc[oo][2*tp], acc[oo][2*tp+1]);
                    int ks = jj >> 4, cp = c >> 4, bsel = (c >> 3) & 1;
                    int lane_ = (c & 7) * 4 + ((jj & 7) >> 1);
                    int idx = bsel * 2 + ((jj & 15) >> 3);
                    stage[((ks * 4 + cp) * 32 + lane_) * 4 + idx] = hi_w;
                }
            }
        }
        __syncthreads();

        // coalesced copy-out
        const uint4* src = (const uint4*)wstage;
        if (m == 0) {
            uint4* gd = g_qf + ((size_t)b * 256 + (n0 >> 4)) * 256;
            #pragma unroll
            for (int k = 0; k < 4; k++) { int i = t + k * 256; gd[i] = src[i]; }
        } else if (m == 1) {
            uint4* gd = g_kf + ((size_t)b * 64 + (n0 >> 6)) * 1024;
            #pragma unroll
            for (int k = 0; k < 4; k++) { int i = t + k * 256; gd[i] = src[i]; }
        } else {
            uint4* gd = g_vf + ((size_t)b * 64 + (n0 >> 6)) * 512;
            #pragma unroll
            for (int k = 0; k < 2; k++) { int i = t + k * 256; gd[i] = src[i]; }
        }
    }
}

// ---------------------------------------------------------------------------
// Inputs (metadata order): x, t(unused), Wq, bq, Wk, bk, Wv, bv
// ---------------------------------------------------------------------------
extern "C" void kernel_launch(void* const* d_in, const int* in_sizes, int n_in,
                              void* d_out, int out_size) {
    const float* x  = (const float*)d_in[0];
    const float* Wq = (const float*)d_in[2];
    const float* bq = (const float*)d_in[3];
    const float* Wk = (const float*)d_in[4];
    const float* bk = (const float*)d_in[5];
    const float* Wv = (const float*)d_in[6];
    const float* bv = (const float*)d_in[7];
    float* out = (float*)d_out;

    cudaFuncSetAttribute(attn_tc, cudaFuncAttributeMaxDynamicSharedMemorySize,
                         98304);
    qkv_kernel<<<dim3(N_ / 64, B_), 256>>>(x, Wq, bq, Wk, bk, Wv, bv);
    attn_tc<<<B_ * 64, 128, 98304>>>(out);
}